// round 9
// baseline (speedup 1.0000x reference)
#include <cuda_runtime.h>

// Problem constants (fixed by the reference: B=2048, S=128, N=B*S).
#define B_ROWS   2048
#define S_ITEMS  128
#define N_ITEMS  (B_ROWS * S_ITEMS)
#define NBLOCKS  (N_ITEMS / 256)         // 1024 blocks, 1 element/thread
#define NWORDS   (N_ITEMS / 32)          // 8192 bitmap words (32KB)
#define FX_SCALE 1073741824.0            // 2^30 fixed-point scale

// Scratch (no device allocation allowed -> __device__ globals, zero-init).
__device__ unsigned int       g_bitmap[NWORDS]; // chosen-item flags (32KB)
__device__ unsigned int       g_arrive;         // barrier arrive counter
__device__ unsigned int       g_release;        // barrier release flag
__device__ unsigned long long g_acc;            // fixed-point accumulator
__device__ unsigned int       g_ticket;         // completion ticket

// Analytic simplification of the reference (valid because y is one-hot per
// assortment row, which setup_inputs guarantees):
//   result = (1/B) * sum_b [ s_b + log(S - rank_b) ]
// where chosen_b = xa at the one-hot position, s_b = sum relu(xa - chosen),
// rank_b = stable ascending rank of chosen within the row.
//
// Structure (single launch):
//   Phase A: coalesced scan of y -> set bit idx-space bitmap (2048 atomicOr);
//            the x gather (the expensive 262K scattered loads) is ALSO issued
//            here since it does not depend on the bitmap — it overlaps the
//            scan and the barrier wait.
//   Barrier: arrive counter + release flag, polled with nanosleep backoff.
//            All 1024 blocks are resident (launch_bounds 256,8; 148*8>=1024).
//   Phase B: bitmap lookup (32KB -> L1-resident after ~256 misses/SM), warp
//            reductions, deterministic fixed-point atomic fold; last ticket
//            block writes out[0] and resets all state for graph replay.
__global__ void __launch_bounds__(256, 8) exp_loss_fused(
    const float* __restrict__ x,
    const float* __restrict__ y,
    const int*   __restrict__ assort,
    float*       __restrict__ out)
{
    const unsigned FULL = 0xffffffffu;
    const int tid  = threadIdx.x;
    const int i    = blockIdx.x * 256 + tid;   // global element id
    const int half = tid >> 7;                 // which of the 2 rows in block
    const int s    = tid & (S_ITEMS - 1);      // position within row
    const int w    = (tid >> 5) & 3;           // warp within row (0..3)
    const int lane = tid & 31;

    __shared__ float ch_s[2];
    __shared__ int   pos_s[2];
    __shared__ float spart[2][4];
    __shared__ int   rpart[2][4];
    __shared__ int   is_last;

    // ---- phase A ----
    int   idx = assort[i];                     // coalesced; kept in register
    float xv  = __ldg(x + idx);                // big scattered gather: issued
                                               // early, overlaps barrier wait
    if (y[i] != 0.0f)                          // exactly 2048 threads grid-wide
        atomicOr(&g_bitmap[i >> 5], 1u << (i & 31));

    // ---- grid barrier (arrive counter + release flag, backoff poll) ----
    __syncthreads();
    if (tid == 0) {
        __threadfence();                       // publish this block's atomicOrs
        unsigned prev = atomicAdd(&g_arrive, 1u);
        if (prev == (unsigned)(NBLOCKS - 1)) {
            atomicExch(&g_release, 1u);        // open the gate
        } else {
            volatile unsigned int* rel = &g_release;
            while (*rel == 0u) __nanosleep(64);
        }
        __threadfence();                       // acquire
    }
    __syncthreads();

    // ---- phase B: bitmap flag (L1-hot), per-row reduction ----
    unsigned bmw  = g_bitmap[idx >> 5];        // first read of each line is
    int      flag = (bmw >> (idx & 31)) & 1u;  // post-barrier -> fresh from L2

    if (flag) {                                // exactly one thread per row
        ch_s[half]  = xv;
        pos_s[half] = s;
    }
    __syncthreads();

    const float ch  = ch_s[half];
    const int   pos = pos_s[half];

    float sv = fmaxf(xv - ch, 0.0f);
    int   rk = (xv < ch) || (xv == ch && s < pos);

#pragma unroll
    for (int o = 16; o; o >>= 1)
        sv += __shfl_xor_sync(FULL, sv, o);
    rk = __reduce_add_sync(FULL, rk);          // REDUX.SUM

    if (lane == 0) {
        spart[half][w] = sv;
        rpart[half][w] = rk;
    }
    __syncthreads();

    // ---- block finalize: deterministic fixed-point atomic fold ----
    if (tid == 0) {
        double acc = 0.0;
#pragma unroll
        for (int h = 0; h < 2; h++) {
            float ssum = 0.0f;
            int   rsum = 0;
#pragma unroll
            for (int j = 0; j < 4; j++) { ssum += spart[h][j]; rsum += rpart[h][j]; }
            acc += (double)(ssum + logf((float)(S_ITEMS - rsum)));
        }
        long long fx = llrint(acc * FX_SCALE); // 2^30 fixed point, no overflow
        (void)atomicAdd(&g_acc, (unsigned long long)fx);  // completes before
        unsigned int t = atomicAdd(&g_ticket, 1u);        // the ticket below
        is_last = (t == (unsigned)(NBLOCKS - 1));
    }
    __syncthreads();

    // ---- last block: write scalar + reset ALL state for next graph replay ----
    if (is_last) {
        // All other blocks have passed their ticket => their bitmap reads and
        // value-atomics are complete; safe to reset everything.
        uint4 z4 = make_uint4(0u, 0u, 0u, 0u);
        uint4* bm4 = reinterpret_cast<uint4*>(g_bitmap);
#pragma unroll
        for (int j = 0; j < (NWORDS / 4) / 256; j++)   // 8 uint4 per thread
            bm4[tid + j * 256] = z4;
        if (tid == 0) {
            long long total = (long long)atomicAdd(&g_acc, 0ull);
            out[0] = (float)((double)total / FX_SCALE / (double)B_ROWS);
            g_acc     = 0ull;
            g_ticket  = 0u;
            g_arrive  = 0u;
            g_release = 0u;
        }
    }
}

extern "C" void kernel_launch(void* const* d_in, const int* in_sizes, int n_in,
                              void* d_out, int out_size)
{
    const float* x      = (const float*)d_in[0];
    const float* y      = (const float*)d_in[1];
    const int*   assort = (const int*)d_in[2];

    exp_loss_fused<<<NBLOCKS, 256>>>(x, y, assort, (float*)d_out);
}

// round 10
// speedup vs baseline: 1.4502x; 1.4502x over previous
#include <cuda_runtime.h>

// Problem constants (fixed by the reference: B=2048, S=128, N=B*S).
#define B_ROWS   2048
#define S_ITEMS  128
#define WARPS_PB 8                       // warps per block (1 row per warp)
#define NBLOCKS  (B_ROWS / WARPS_PB)     // 256 blocks
#define FX_SCALE 1073741824.0            // 2^30 fixed-point scale

// Scratch (no device allocation allowed -> __device__ globals, zero-init).
__device__ unsigned long long g_acc;     // fixed-point deterministic accumulator
__device__ unsigned int       g_ticket;  // completion ticket

// Analytic simplification of the reference (valid because y is one-hot per
// assortment row, which setup_inputs guarantees):
//   result = (1/B) * sum_b [ s_b + log(S - rank_b) ]
// where
//   chosen_b = xa at the one-hot position,
//   s_b      = sum_k relu(xa[b,k] - chosen_b),
//   rank_b   = stable ascending rank of chosen within the row
//            = #{k: xa<chosen} + #{k<pos: xa==chosen}.
//
// Shape chosen from measured evidence:
//  * row-per-warp, 4 items per lane: one int4 index load + 8 independent
//    scattered gathers in flight per thread (MLP ~8) — measured ~2us faster
//    than the 1-item/thread high-occupancy shape for this permutation gather.
//  * fixed-point int64 atomic fold (order-independent integer adds -> bit-
//    deterministic) instead of fence + partial array + tree: tail ~0.5us.
//  * NO grid barrier (measured ~3us cost in both styles tried).
__global__ void __launch_bounds__(256) exp_loss_fused(
    const float* __restrict__ x,
    const float* __restrict__ y,
    const int*   __restrict__ assort,
    float*       __restrict__ out)
{
    const unsigned FULL = 0xffffffffu;
    const int tid    = threadIdx.x;
    const int lane   = tid & 31;
    const int warpid = tid >> 5;                        // 0..7
    const int row    = blockIdx.x * WARPS_PB + warpid;  // 0..2047

    // ---- per-row computation: 1 int4 index load + 8 gathers, all batched ----
    const int4* arow = reinterpret_cast<const int4*>(assort + row * S_ITEMS);
    int4 a = arow[lane];
    int idx4[4] = {a.x, a.y, a.z, a.w};

    float xv[4], yv[4];
#pragma unroll
    for (int i = 0; i < 4; i++) xv[i] = __ldg(x + idx4[i]);
#pragma unroll
    for (int i = 0; i < 4; i++) yv[i] = __ldg(y + idx4[i]);

    // Locate the one-hot item: local value/position, one ballot + 2 shfl.
    float lch  = 0.0f;
    int   lpos = -1;
#pragma unroll
    for (int i = 0; i < 4; i++) {
        lch += xv[i] * yv[i];              // exact: other terms are +-0
        if (yv[i] != 0.0f) lpos = lane * 4 + i;
    }
    unsigned bal = __ballot_sync(FULL, lpos >= 0);
    int   src = __ffs(bal) - 1;            // exactly one lane holds the item
    float ch  = __shfl_sync(FULL, lch,  src);
    int   pos = __shfl_sync(FULL, lpos, src);

    // s = sum relu(xa - chosen);  rank = stable ascending rank of chosen.
    float sv = 0.0f;
    int   rk = 0;
#pragma unroll
    for (int i = 0; i < 4; i++) {
        sv += fmaxf(xv[i] - ch, 0.0f);
        int gi = lane * 4 + i;
        rk += (xv[i] < ch) || (xv[i] == ch && gi < pos);
    }
#pragma unroll
    for (int o = 16; o; o >>= 1)
        sv += __shfl_xor_sync(FULL, sv, o);
    rk = __reduce_add_sync(FULL, rk);      // REDUX.SUM

    // ---- block fold: 8 warp values -> one fixed-point atomic pair ----
    __shared__ float warpval[WARPS_PB];
    if (lane == 0)
        warpval[warpid] = sv + logf((float)(S_ITEMS - rk));
    __syncthreads();

    if (tid == 0) {
        double acc = 0.0;
#pragma unroll
        for (int i = 0; i < WARPS_PB; i++) acc += (double)warpval[i];
        long long fx = llrint(acc * FX_SCALE);   // 2^30 fixed point
        // Returning atomic completes at L2 before the ticket atomic below,
        // so the last ticket implies every block's value-add is visible.
        (void)atomicAdd(&g_acc, (unsigned long long)fx);
        unsigned int t = atomicAdd(&g_ticket, 1u);
        if (t == (unsigned)(NBLOCKS - 1)) {
            long long total = (long long)atomicAdd(&g_acc, 0ull);
            out[0] = (float)((double)total / FX_SCALE / (double)B_ROWS);
            g_acc    = 0ull;               // reset for next graph replay
            g_ticket = 0u;
        }
    }
}

extern "C" void kernel_launch(void* const* d_in, const int* in_sizes, int n_in,
                              void* d_out, int out_size)
{
    const float* x      = (const float*)d_in[0];
    const float* y      = (const float*)d_in[1];
    const int*   assort = (const int*)d_in[2];

    exp_loss_fused<<<NBLOCKS, 256>>>(x, y, assort, (float*)d_out);
}